// round 11
// baseline (speedup 1.0000x reference)
#include <cuda_runtime.h>
#include <cuda_bf16.h>
#include <mma.h>
#include <math.h>

using namespace nvcuda;

// Problem constants
#define B   32
#define C   512
#define HW  196          // 14*14
#define D   8192
#define KP  208          // HW padded to 13*16
#define BC  (B * C)      // 16384
#define LDS2 68          // stage row stride (floats)
#define STAGE_F (64 * LDS2)              // floats per batch stage
// chunk ring: 2 stages x 4 tiles x (64 rows x 24 cols) bf16
#define LDC 24
#define CHS (64 * LDC)                   // elems per tile chunk (1536)
#define CHSTG (4 * CHS)                  // elems per ring stage  (6144)
#define SMEM_DYN (2*CHSTG*2 + 4*STAGE_F*4)    // 24576 + 69632 = 94208

// ---------------- device scratch (no allocations allowed) ----------------
__device__ int   g_h[2][C];
__device__ float g_s[2][C];
__device__ __align__(32) __nv_bfloat16 g_Ah[(size_t)BC * KP];  // hi part
__device__ __align__(32) __nv_bfloat16 g_Al[(size_t)BC * KP];  // lo part
__device__ float g_Yt[(size_t)D * B];           // [d][b]  (b innermost)

__device__ __forceinline__ void cp16(unsigned dst, const void* src) {
    asm volatile("cp.async.cg.shared.global [%0], [%1], 16;" :: "r"(dst), "l"(src));
}

// ---------------- 1. fused: split-pack x, extract (h,s), zero Yt ----------------
__global__ void setup_kernel(const float* __restrict__ x,
                             const float* __restrict__ S1,
                             const float* __restrict__ S2) {
    int bx = blockIdx.x;
    int t  = threadIdx.x;
    if (bx < 1024) {
        // ---- prep: 16 x-rows per block, split into bf16 hi/lo ----
        int base = bx * 16;
        for (int e = t; e < 16 * KP; e += 256) {
            int r = e / KP, k = e - r * KP;
            int bc = base + r;
            float v = (k < HW) ? x[(size_t)bc * HW + k] : 0.f;
            __nv_bfloat16 hi = __float2bfloat16(v);
            float lo = v - __bfloat162float(hi);
            g_Ah[(size_t)bc * KP + k] = hi;
            g_Al[(size_t)bc * KP + k] = __float2bfloat16(lo);
        }
        return;
    }
    if (bx < 1024 + 2048) {
        // ---- extract: 2 blocks per sketch row; 4 independent loads (MLP=4) ----
        int q    = bx - 1024;
        int row  = q >> 1;
        int half = q & 1;
        int mat = row >> 9;
        int r   = row & (C - 1);
        const float4* p = (const float4*)((mat ? S2 : S1) + (size_t)r * D) + half * 1024;
        float4 v[4];
        #pragma unroll
        for (int u = 0; u < 4; u++) v[u] = p[t + u * 256];
        int   idx = -1;
        float sg  = 0.f;
        #pragma unroll
        for (int u = 0; u < 4; u++) {
            int c = half * 4096 + 4 * (t + u * 256);
            if (fabsf(v[u].x) > 0.5f) { idx = c + 0; sg = v[u].x; }
            if (fabsf(v[u].y) > 0.5f) { idx = c + 1; sg = v[u].y; }
            if (fabsf(v[u].z) > 0.5f) { idx = c + 2; sg = v[u].z; }
            if (fabsf(v[u].w) > 0.5f) { idx = c + 3; sg = v[u].w; }
        }
        if (idx >= 0) {                          // exactly one thread (whole grid) hits per row
            g_h[mat][r] = idx;
            g_s[mat][r] = sg;
        }
        return;
    }
    // ---- zero Yt: 256 blocks x 256 thr x float4 ----
    int zb = bx - 1024 - 2048;
    float4* y4 = (float4*)g_Yt;
    y4[zb * 256 + t] = make_float4(0.f, 0.f, 0.f, 0.f);
}

// stage one 16-wide K-chunk (4 tiles, or 2 if diag) into ring buffer `buf`
__device__ __forceinline__ void stage_chunk(unsigned chBase, int buf, int kc,
                                            int b, int gm, int gn, bool diag, int tid) {
    int ncp = diag ? 256 : 512;
    #pragma unroll
    for (int e = tid; e < ncp; e += 256) {       // 1 or 2 iterations
        int tile = e >> 7;                       // 0..3 : Ahi, Ali, Bhi, Bli
        int rr   = (e >> 1) & 63;
        int half = e & 1;
        const __nv_bfloat16* gsrc = (tile & 1) ? g_Al : g_Ah;
        int grow = ((tile < 2) ? gm : gn) + rr;
        const char* src = (const char*)(gsrc + ((size_t)b * C + grow) * KP + kc * 16 + half * 8);
        unsigned dst = chBase + (unsigned)((buf * CHSTG + tile * CHS + rr * LDC + half * 8) * 2);
        cp16(dst, src);
    }
    asm volatile("cp.async.commit_group;");
}

// ---------------- 2. Gram (bf16-split wmma), k-chunk pipelined, v4 red scatter ----------------
//   G = Xh.Xh^T + Xh.Xl^T + Xl.Xh^T  (drops Xl.Xl^T, ~2^-16 relative)
__global__ __launch_bounds__(256, 2) void gram_scatter() {
    int bg = blockIdx.y;                         // batch group: b = bg*4 + bi
    int ti = 0, rem = blockIdx.x;                // upper-triangular tile pair, ti <= tj
    while (rem >= 8 - ti) { rem -= 8 - ti; ti++; }
    int tj = ti + rem;
    bool diag = (ti == tj);

    extern __shared__ __align__(16) __nv_bfloat16 sm[];
    __nv_bfloat16* ch = sm;                      // ring: 2 x 4 x (64 x LDC)
    float* stage = (float*)(sm + 2 * CHSTG);     // 4 x (64 x LDS2) floats
    __shared__ int   hh[256];
    __shared__ float ss[256];

    int tid  = threadIdx.x;
    int warp = tid >> 5;
    int wr   = warp >> 1;        // 0..3 (m, 16 rows)
    int wc   = warp & 1;         // 0..1 (n, 32 cols)

    unsigned chBase = (unsigned)__cvta_generic_to_shared(ch);

    int gm = ti * 64, gn = tj * 64;
    if (tid < 64) {
        hh[tid]       = g_h[0][gm + tid];        // h1 over row range
        hh[64 + tid]  = g_h[1][gn + tid];        // h2 over col range
        hh[128 + tid] = g_h[0][gn + tid];        // h1 over col range (mirror)
        hh[192 + tid] = g_h[1][gm + tid];        // h2 over row range (mirror)
        ss[tid]       = g_s[0][gm + tid];
        ss[64 + tid]  = g_s[1][gn + tid];
        ss[128 + tid] = g_s[0][gn + tid];
        ss[192 + tid] = g_s[1][gm + tid];
    }

    int tPh = diag ? 0 : 2;      // B-hi tile index
    int tPl = diag ? 1 : 3;      // B-lo tile index

    #pragma unroll 1
    for (int bi = 0; bi < 4; bi++) {
        int b = bg * 4 + bi;
        __syncthreads();                         // prev batch MMA (chunk 12, buf 0) done
        stage_chunk(chBase, 0, 0, b, gm, gn, diag, tid);   // prologue chunk 0

        wmma::fragment<wmma::accumulator, 16, 16, 16, float> a0hh, a0hl, a0lh, a1hh, a1hl, a1lh;
        wmma::fill_fragment(a0hh, 0.f); wmma::fill_fragment(a0hl, 0.f); wmma::fill_fragment(a0lh, 0.f);
        wmma::fill_fragment(a1hh, 0.f); wmma::fill_fragment(a1hl, 0.f); wmma::fill_fragment(a1lh, 0.f);

        #pragma unroll 1
        for (int kc = 0; kc < 13; kc++) {
            int buf = kc & 1;
            asm volatile("cp.async.wait_group 0;" ::: "memory");   // chunk kc landed
            __syncthreads();                                        // visible to all; prev MMA done
            if (kc < 12)
                stage_chunk(chBase, buf ^ 1, kc + 1, b, gm, gn, diag, tid);

            const __nv_bfloat16* cb = ch + buf * CHSTG;
            wmma::fragment<wmma::matrix_a, 16, 16, 16, __nv_bfloat16, wmma::row_major> ah, al;
            wmma::fragment<wmma::matrix_b, 16, 16, 16, __nv_bfloat16, wmma::col_major> bh0, bh1, bl0, bl1;
            wmma::load_matrix_sync(ah,  cb + 0 * CHS + (wr * 16) * LDC, LDC);
            wmma::load_matrix_sync(al,  cb + 1 * CHS + (wr * 16) * LDC, LDC);
            wmma::load_matrix_sync(bh0, cb + tPh * CHS + (wc * 32) * LDC, LDC);
            wmma::load_matrix_sync(bh1, cb + tPh * CHS + (wc * 32 + 16) * LDC, LDC);
            wmma::load_matrix_sync(bl0, cb + tPl * CHS + (wc * 32) * LDC, LDC);
            wmma::load_matrix_sync(bl1, cb + tPl * CHS + (wc * 32 + 16) * LDC, LDC);
            wmma::mma_sync(a0hh, ah, bh0, a0hh);     // all 6 independent
            wmma::mma_sync(a1hh, ah, bh1, a1hh);
            wmma::mma_sync(a0hl, ah, bl0, a0hl);
            wmma::mma_sync(a1hl, ah, bl1, a1hl);
            wmma::mma_sync(a0lh, al, bh0, a0lh);
            wmma::mma_sync(a1lh, al, bh1, a1lh);
        }
        #pragma unroll
        for (int e = 0; e < a0hh.num_elements; e++) {
            a0hh.x[e] += a0hl.x[e] + a0lh.x[e];
            a1hh.x[e] += a1hl.x[e] + a1lh.x[e];
        }

        float* st = stage + bi * STAGE_F;
        wmma::store_matrix_sync(&st[(wr * 16) * LDS2 + wc * 32],      a0hh, LDS2, wmma::mem_row_major);
        wmma::store_matrix_sync(&st[(wr * 16) * LDS2 + wc * 32 + 16], a1hh, LDS2, wmma::mem_row_major);
    }
    __syncthreads();

    // ---- scatter: one red.v4 per (pair, orientation) covering 4 batches ----
    float* Ybase = g_Yt + bg * 4;
    #pragma unroll 2
    for (int e = tid; e < 4096; e += 256) {
        int r = e >> 6, c = e & 63;
        int off = r * LDS2 + c;
        float v0 = stage[0 * STAGE_F + off];
        float v1 = stage[1 * STAGE_F + off];
        float v2 = stage[2 * STAGE_F + off];
        float v3 = stage[3 * STAGE_F + off];
        int   d1 = (hh[r] + hh[64 + c]) & (D - 1);
        float w1 = ss[r] * ss[64 + c];
        float* p1 = Ybase + (size_t)d1 * B;
        asm volatile("red.global.add.v4.f32 [%0], {%1, %2, %3, %4};"
                     :: "l"(p1), "f"(v0 * w1), "f"(v1 * w1), "f"(v2 * w1), "f"(v3 * w1)
                     : "memory");
        if (!diag) {
            int   d2 = (hh[128 + c] + hh[192 + r]) & (D - 1);
            float w2 = ss[128 + c] * ss[192 + r];
            float* p2 = Ybase + (size_t)d2 * B;
            asm volatile("red.global.add.v4.f32 [%0], {%1, %2, %3, %4};"
                         :: "l"(p2), "f"(v0 * w2), "f"(v1 * w2), "f"(v2 * w2), "f"(v3 * w2)
                         : "memory");
        }
    }
}

// ---------------- 3. signed sqrt + L2 normalize ----------------
__global__ void finalize_kernel(float* __restrict__ out) {   // 32 blocks x 256 thr
    __shared__ float ysh[D];
    __shared__ float red[8];
    int b = blockIdx.x;
    int t = threadIdx.x;
    float ssum = 0.f;
    for (int d = t; d < D; d += 256) {
        float y  = g_Yt[(size_t)d * B + b];
        float sg = (y > 0.f) ? 1.f : ((y < 0.f) ? -1.f : 0.f);
        float v  = sg * sqrtf(fabsf(y) + 1e-8f);
        ysh[d] = v;
        ssum += v * v;
    }
    #pragma unroll
    for (int o = 16; o; o >>= 1) ssum += __shfl_xor_sync(0xffffffffu, ssum, o);
    if ((t & 31) == 0) red[t >> 5] = ssum;
    __syncthreads();
    if (t < 32) {
        float v2 = (t < 8) ? red[t] : 0.f;
        #pragma unroll
        for (int o = 4; o; o >>= 1) v2 += __shfl_xor_sync(0xffffffffu, v2, o);
        if (t == 0) red[0] = v2;
    }
    __syncthreads();
    float inv = 1.f / fmaxf(sqrtf(red[0]), 1e-12f);
    for (int d = t; d < D; d += 256)
        out[(size_t)b * D + d] = ysh[d] * inv;
}

// ---------------- launcher ----------------
extern "C" void kernel_launch(void* const* d_in, const int* in_sizes, int n_in,
                              void* d_out, int out_size) {
    const float* x  = nullptr;
    const float* S1 = nullptr;
    const float* S2 = nullptr;
    for (int i = 0; i < n_in; i++) {
        if (in_sizes[i] == B * C * HW) { x = (const float*)d_in[i]; }
        else if (!S1)                  { S1 = (const float*)d_in[i]; }
        else                           { S2 = (const float*)d_in[i]; }
    }
    float* out = (float*)d_out;

    static int smem_set = 0;
    if (!smem_set) {
        cudaFuncSetAttribute(gram_scatter, cudaFuncAttributeMaxDynamicSharedMemorySize, SMEM_DYN);
        smem_set = 1;
    }

    setup_kernel   <<<1024 + 2048 + 256, 256>>>(x, S1, S2);
    gram_scatter   <<<dim3(36, 8), 256, SMEM_DYN>>>();
    finalize_kernel<<<B, 256>>>(out);
}

// round 14
// speedup vs baseline: 1.0935x; 1.0935x over previous
#include <cuda_runtime.h>
#include <cuda_bf16.h>
#include <mma.h>
#include <math.h>

using namespace nvcuda;

// Problem constants
#define B   32
#define C   512
#define HW  196          // 14*14
#define D   8192
#define KP  208          // HW padded to 13*16
#define LDK 216          // smem row stride in bf16 (208 + 8 pad)
#define BC  (B * C)      // 16384
#define LDS2 68          // stage row stride (floats)
#define STAGE_F (64 * LDS2)              // floats per batch stage
#define SMEM_DYN (4*64*LDK*2 + 4*STAGE_F*4)   // 110592 + 69632 = 180224

// ---------------- device scratch (no allocations allowed) ----------------
__device__ int   g_h[2][C];
__device__ float g_s[2][C];
__device__ __align__(32) __nv_bfloat16 g_Ah[(size_t)BC * KP];  // hi part
__device__ __align__(32) __nv_bfloat16 g_Al[(size_t)BC * KP];  // lo part
__device__ float g_Yt[(size_t)D * B];           // [d][b]  (b innermost)

// ---------------- 0. dummy: shifts the ncu -s6 sample onto gram_scatter ----------------
__global__ void dummy_kernel() {}

// ---------------- 1. fused: split-pack x, extract (h,s), zero Yt ----------------
__global__ void setup_kernel(const float* __restrict__ x,
                             const float* __restrict__ S1,
                             const float* __restrict__ S2) {
    int bx = blockIdx.x;
    int t  = threadIdx.x;
    if (bx < 1024) {
        // ---- prep: 16 x-rows per block, split into bf16 hi/lo ----
        int base = bx * 16;
        for (int e = t; e < 16 * KP; e += 256) {
            int r = e / KP, k = e - r * KP;
            int bc = base + r;
            float v = (k < HW) ? x[(size_t)bc * HW + k] : 0.f;
            __nv_bfloat16 hi = __float2bfloat16(v);
            float lo = v - __bfloat162float(hi);
            g_Ah[(size_t)bc * KP + k] = hi;
            g_Al[(size_t)bc * KP + k] = __float2bfloat16(lo);
        }
        return;
    }
    if (bx < 1024 + 2048) {
        // ---- extract: 2 blocks per sketch row; 4 independent loads (MLP=4) ----
        int q    = bx - 1024;
        int row  = q >> 1;
        int half = q & 1;
        int mat = row >> 9;
        int r   = row & (C - 1);
        const float4* p = (const float4*)((mat ? S2 : S1) + (size_t)r * D) + half * 1024;
        float4 v[4];
        #pragma unroll
        for (int u = 0; u < 4; u++) v[u] = p[t + u * 256];
        int   idx = -1;
        float sg  = 0.f;
        #pragma unroll
        for (int u = 0; u < 4; u++) {
            int c = half * 4096 + 4 * (t + u * 256);
            if (fabsf(v[u].x) > 0.5f) { idx = c + 0; sg = v[u].x; }
            if (fabsf(v[u].y) > 0.5f) { idx = c + 1; sg = v[u].y; }
            if (fabsf(v[u].z) > 0.5f) { idx = c + 2; sg = v[u].z; }
            if (fabsf(v[u].w) > 0.5f) { idx = c + 3; sg = v[u].w; }
        }
        if (idx >= 0) {                          // exactly one thread (whole grid) hits per row
            g_h[mat][r] = idx;
            g_s[mat][r] = sg;
        }
        return;
    }
    // ---- zero Yt: 256 blocks x 256 thr x float4 ----
    int zb = bx - 1024 - 2048;
    float4* y4 = (float4*)g_Yt;
    y4[zb * 256 + t] = make_float4(0.f, 0.f, 0.f, 0.f);
}

// ---------------- 2. Gram (bf16-split wmma), 4-batch groups, v4 red scatter ----------------
//   G = Xh.Xh^T + Xh.Xl^T + Xl.Xh^T  (drops Xl.Xl^T, ~2^-16 relative)
__global__ __launch_bounds__(256, 1) void gram_scatter() {
    int bg = blockIdx.y;                         // batch group: b = bg*4 + bi
    int ti = 0, rem = blockIdx.x;                // upper-triangular tile pair, ti <= tj
    while (rem >= 8 - ti) { rem -= 8 - ti; ti++; }
    int tj = ti + rem;
    bool diag = (ti == tj);

    extern __shared__ __align__(16) __nv_bfloat16 sm[];
    __nv_bfloat16* Ahi = sm;                     // 64 x LDK each
    __nv_bfloat16* Ali = sm + 1 * 64 * LDK;
    __nv_bfloat16* Bhj = sm + 2 * 64 * LDK;
    __nv_bfloat16* Blj = sm + 3 * 64 * LDK;
    float* stage = (float*)(sm + 4 * 64 * LDK);  // 4 x (64 x LDS2) floats
    __shared__ int   hh[256];
    __shared__ float ss[256];

    int tid  = threadIdx.x;
    int warp = tid >> 5;
    int wr   = warp >> 1;        // 0..3 (m, 16 rows)
    int wc   = warp & 1;         // 0..1 (n, 32 cols)

    int gm = ti * 64, gn = tj * 64;
    if (tid < 64) {
        hh[tid]       = g_h[0][gm + tid];        // h1 over row range
        hh[64 + tid]  = g_h[1][gn + tid];        // h2 over col range
        hh[128 + tid] = g_h[0][gn + tid];        // h1 over col range (mirror)
        hh[192 + tid] = g_h[1][gm + tid];        // h2 over row range (mirror)
        ss[tid]       = g_s[0][gm + tid];
        ss[64 + tid]  = g_s[1][gn + tid];
        ss[128 + tid] = g_s[0][gn + tid];
        ss[192 + tid] = g_s[1][gm + tid];
    }

    #pragma unroll 1
    for (int bi = 0; bi < 4; bi++) {
        int b = bg * 4 + bi;
        __syncthreads();                         // prev iter's tile reads done (and hh/ss ready)
        // ---- stage tiles for this batch ----
        const __nv_bfloat16* gHi = g_Ah + (size_t)b * C * KP;
        const __nv_bfloat16* gLo = g_Al + (size_t)b * C * KP;
        {
            const __nv_bfloat16* sa_h = gHi + (size_t)ti * 64 * KP;
            const __nv_bfloat16* sa_l = gLo + (size_t)ti * 64 * KP;
            const __nv_bfloat16* sb_h = gHi + (size_t)tj * 64 * KP;
            const __nv_bfloat16* sb_l = gLo + (size_t)tj * 64 * KP;
            #pragma unroll 2
            for (int idx = tid; idx < 64 * 26; idx += 256) {
                int row = idx / 26, q = idx - row * 26;
                int so = row * KP + q * 8, dof = row * LDK + q * 8;
                *(uint4*)&Ahi[dof] = *(const uint4*)&sa_h[so];
                *(uint4*)&Ali[dof] = *(const uint4*)&sa_l[so];
                if (!diag) {
                    *(uint4*)&Bhj[dof] = *(const uint4*)&sb_h[so];
                    *(uint4*)&Blj[dof] = *(const uint4*)&sb_l[so];
                }
            }
        }
        __syncthreads();

        const __nv_bfloat16* Ph = diag ? Ahi : Bhj;
        const __nv_bfloat16* Pl = diag ? Ali : Blj;

        // 2 output tiles x 3 independent product chains
        wmma::fragment<wmma::accumulator, 16, 16, 16, float> a0hh, a0hl, a0lh, a1hh, a1hl, a1lh;
        wmma::fill_fragment(a0hh, 0.f); wmma::fill_fragment(a0hl, 0.f); wmma::fill_fragment(a0lh, 0.f);
        wmma::fill_fragment(a1hh, 0.f); wmma::fill_fragment(a1hl, 0.f); wmma::fill_fragment(a1lh, 0.f);

        #pragma unroll
        for (int kc = 0; kc < 13; kc++) {
            int ko = kc * 16;
            wmma::fragment<wmma::matrix_a, 16, 16, 16, __nv_bfloat16, wmma::row_major> ah, al;
            wmma::fragment<wmma::matrix_b, 16, 16, 16, __nv_bfloat16, wmma::col_major> bh0, bh1, bl0, bl1;
            wmma::load_matrix_sync(ah,  &Ahi[(wr * 16) * LDK + ko], LDK);
            wmma::load_matrix_sync(al,  &Ali[(wr * 16) * LDK + ko], LDK);
            wmma::load_matrix_sync(bh0, &Ph[(wc * 32) * LDK + ko], LDK);
            wmma::load_matrix_sync(bh1, &Ph[(wc * 32 + 16) * LDK + ko], LDK);
            wmma::load_matrix_sync(bl0, &Pl[(wc * 32) * LDK + ko], LDK);
            wmma::load_matrix_sync(bl1, &Pl[(wc * 32 + 16) * LDK + ko], LDK);
            wmma::mma_sync(a0hh, ah, bh0, a0hh);     // all 6 independent
            wmma::mma_sync(a1hh, ah, bh1, a1hh);
            wmma::mma_sync(a0hl, ah, bl0, a0hl);
            wmma::mma_sync(a1hl, ah, bl1, a1hl);
            wmma::mma_sync(a0lh, al, bh0, a0lh);
            wmma::mma_sync(a1lh, al, bh1, a1lh);
        }
        #pragma unroll
        for (int e = 0; e < a0hh.num_elements; e++) {
            a0hh.x[e] += a0hl.x[e] + a0lh.x[e];
            a1hh.x[e] += a1hl.x[e] + a1lh.x[e];
        }

        float* st = stage + bi * STAGE_F;
        wmma::store_matrix_sync(&st[(wr * 16) * LDS2 + wc * 32],      a0hh, LDS2, wmma::mem_row_major);
        wmma::store_matrix_sync(&st[(wr * 16) * LDS2 + wc * 32 + 16], a1hh, LDS2, wmma::mem_row_major);
    }
    __syncthreads();

    // ---- scatter: one red.v4 per (pair, orientation) covering 4 batches ----
    float* Ybase = g_Yt + bg * 4;
    #pragma unroll 4
    for (int e = tid; e < 4096; e += 256) {
        int r = e >> 6, c = e & 63;
        int off = r * LDS2 + c;
        float v0 = stage[0 * STAGE_F + off];
        float v1 = stage[1 * STAGE_F + off];
        float v2 = stage[2 * STAGE_F + off];
        float v3 = stage[3 * STAGE_F + off];
        int   d1 = (hh[r] + hh[64 + c]) & (D - 1);
        float w1 = ss[r] * ss[64 + c];
        float* p1 = Ybase + (size_t)d1 * B;
        asm volatile("red.global.add.v4.f32 [%0], {%1, %2, %3, %4};"
                     :: "l"(p1), "f"(v0 * w1), "f"(v1 * w1), "f"(v2 * w1), "f"(v3 * w1)
                     : "memory");
        if (!diag) {
            int   d2 = (hh[128 + c] + hh[192 + r]) & (D - 1);
            float w2 = ss[128 + c] * ss[192 + r];
            float* p2 = Ybase + (size_t)d2 * B;
            asm volatile("red.global.add.v4.f32 [%0], {%1, %2, %3, %4};"
                         :: "l"(p2), "f"(v0 * w2), "f"(v1 * w2), "f"(v2 * w2), "f"(v3 * w2)
                         : "memory");
        }
    }
}

// ---------------- 3. signed sqrt + L2 normalize ----------------
__global__ void finalize_kernel(float* __restrict__ out) {   // 32 blocks x 256 thr
    __shared__ float ysh[D];
    __shared__ float red[8];
    int b = blockIdx.x;
    int t = threadIdx.x;
    float ssum = 0.f;
    for (int d = t; d < D; d += 256) {
        float y  = g_Yt[(size_t)d * B + b];
        float sg = (y > 0.f) ? 1.f : ((y < 0.f) ? -1.f : 0.f);
        float v  = sg * sqrtf(fabsf(y) + 1e-8f);
        ysh[d] = v;
        ssum += v * v;
    }
    #pragma unroll
    for (int o = 16; o; o >>= 1) ssum += __shfl_xor_sync(0xffffffffu, ssum, o);
    if ((t & 31) == 0) red[t >> 5] = ssum;
    __syncthreads();
    if (t < 32) {
        float v2 = (t < 8) ? red[t] : 0.f;
        #pragma unroll
        for (int o = 4; o; o >>= 1) v2 += __shfl_xor_sync(0xffffffffu, v2, o);
        if (t == 0) red[0] = v2;
    }
    __syncthreads();
    float inv = 1.f / fmaxf(sqrtf(red[0]), 1e-12f);
    for (int d = t; d < D; d += 256)
        out[(size_t)b * D + d] = ysh[d] * inv;
}

// ---------------- launcher ----------------
extern "C" void kernel_launch(void* const* d_in, const int* in_sizes, int n_in,
                              void* d_out, int out_size) {
    const float* x  = nullptr;
    const float* S1 = nullptr;
    const float* S2 = nullptr;
    for (int i = 0; i < n_in; i++) {
        if (in_sizes[i] == B * C * HW) { x = (const float*)d_in[i]; }
        else if (!S1)                  { S1 = (const float*)d_in[i]; }
        else                           { S2 = (const float*)d_in[i]; }
    }
    float* out = (float*)d_out;

    static int smem_set = 0;
    if (!smem_set) {
        cudaFuncSetAttribute(gram_scatter, cudaFuncAttributeMaxDynamicSharedMemorySize, SMEM_DYN);
        smem_set = 1;
    }

    dummy_kernel   <<<1, 32>>>();                // shifts ncu sample to gram_scatter
    setup_kernel   <<<1024 + 2048 + 256, 256>>>(x, S1, S2);
    gram_scatter   <<<dim3(36, 8), 256, SMEM_DYN>>>();
    finalize_kernel<<<B, 256>>>(out);
}

// round 15
// speedup vs baseline: 1.1711x; 1.0710x over previous
#include <cuda_runtime.h>
#include <cuda_bf16.h>
#include <mma.h>
#include <math.h>

using namespace nvcuda;

// Problem constants
#define B   32
#define C   512
#define HW  196          // 14*14
#define D   8192
#define KP  208          // HW padded to 13*16
#define LDK 216          // smem row stride in bf16 (208 + 8 pad)
#define BC  (B * C)      // 16384
#define LDS2 68          // stage row stride (floats)
#define STAGE_F (64 * LDS2)              // floats per batch stage
#define SMEM_DYN (4*64*LDK*2 + 4*STAGE_F*4)   // 110592 + 69632 = 180224

// ---------------- device scratch (no allocations allowed) ----------------
__device__ int   g_h[2][C];
__device__ float g_s[2][C];
__device__ __align__(32) __nv_bfloat16 g_Ah[(size_t)BC * KP];  // hi part
__device__ __align__(32) __nv_bfloat16 g_Al[(size_t)BC * KP];  // lo part
__device__ float g_Yt[(size_t)D * B];           // [d][b]  (b innermost)
__device__ float g_Ys[(size_t)B * D];           // signed-sqrt values, [b][d]
__device__ float g_norm[B];                      // per-batch sum of squares

// ---------------- 0. dummy: positions gram_scatter at global launch index 3 ----------------
__global__ void dummy_kernel() {}

// ---------------- 1. fused: split-pack x, extract (h,s), zero Yt/norm ----------------
__global__ void setup_kernel(const float* __restrict__ x,
                             const float* __restrict__ S1,
                             const float* __restrict__ S2) {
    int bx = blockIdx.x;
    int t  = threadIdx.x;
    if (bx < 1024) {
        // ---- prep: 16 x-rows per block, split into bf16 hi/lo ----
        int base = bx * 16;
        for (int e = t; e < 16 * KP; e += 256) {
            int r = e / KP, k = e - r * KP;
            int bc = base + r;
            float v = (k < HW) ? x[(size_t)bc * HW + k] : 0.f;
            __nv_bfloat16 hi = __float2bfloat16(v);
            float lo = v - __bfloat162float(hi);
            g_Ah[(size_t)bc * KP + k] = hi;
            g_Al[(size_t)bc * KP + k] = __float2bfloat16(lo);
        }
        return;
    }
    if (bx < 1024 + 2048) {
        // ---- extract: 2 blocks per sketch row; 4 independent loads (MLP=4) ----
        int q    = bx - 1024;
        int row  = q >> 1;
        int half = q & 1;
        int mat = row >> 9;
        int r   = row & (C - 1);
        const float4* p = (const float4*)((mat ? S2 : S1) + (size_t)r * D) + half * 1024;
        float4 v[4];
        #pragma unroll
        for (int u = 0; u < 4; u++) v[u] = p[t + u * 256];
        int   idx = -1;
        float sg  = 0.f;
        #pragma unroll
        for (int u = 0; u < 4; u++) {
            int c = half * 4096 + 4 * (t + u * 256);
            if (fabsf(v[u].x) > 0.5f) { idx = c + 0; sg = v[u].x; }
            if (fabsf(v[u].y) > 0.5f) { idx = c + 1; sg = v[u].y; }
            if (fabsf(v[u].z) > 0.5f) { idx = c + 2; sg = v[u].z; }
            if (fabsf(v[u].w) > 0.5f) { idx = c + 3; sg = v[u].w; }
        }
        if (idx >= 0) {                          // exactly one thread (whole grid) hits per row
            g_h[mat][r] = idx;
            g_s[mat][r] = sg;
        }
        return;
    }
    // ---- zero Yt (+ norm): 256 blocks x 256 thr x float4 ----
    int zb = bx - 1024 - 2048;
    float4* y4 = (float4*)g_Yt;
    y4[zb * 256 + t] = make_float4(0.f, 0.f, 0.f, 0.f);
    if (zb == 0 && t < B) g_norm[t] = 0.f;
}

// ---------------- 2. Gram (bf16-split wmma), 4-batch groups, v4 red scatter ----------------
//   G = Xh.Xh^T + Xh.Xl^T + Xl.Xh^T  (drops Xl.Xl^T, ~2^-16 relative)
__global__ __launch_bounds__(256, 1) void gram_scatter() {
    int bg = blockIdx.y;                         // batch group: b = bg*4 + bi
    int ti = 0, rem = blockIdx.x;                // upper-triangular tile pair, ti <= tj
    while (rem >= 8 - ti) { rem -= 8 - ti; ti++; }
    int tj = ti + rem;
    bool diag = (ti == tj);

    extern __shared__ __align__(16) __nv_bfloat16 sm[];
    __nv_bfloat16* Ahi = sm;                     // 64 x LDK each
    __nv_bfloat16* Ali = sm + 1 * 64 * LDK;
    __nv_bfloat16* Bhj = sm + 2 * 64 * LDK;
    __nv_bfloat16* Blj = sm + 3 * 64 * LDK;
    float* stage = (float*)(sm + 4 * 64 * LDK);  // 4 x (64 x LDS2) floats
    __shared__ int   hh[256];
    __shared__ float ss[256];

    int tid  = threadIdx.x;
    int warp = tid >> 5;
    int wr   = warp >> 1;        // 0..3 (m, 16 rows)
    int wc   = warp & 1;         // 0..1 (n, 32 cols)

    int gm = ti * 64, gn = tj * 64;
    if (tid < 64) {
        hh[tid]       = g_h[0][gm + tid];        // h1 over row range
        hh[64 + tid]  = g_h[1][gn + tid];        // h2 over col range
        hh[128 + tid] = g_h[0][gn + tid];        // h1 over col range (mirror)
        hh[192 + tid] = g_h[1][gm + tid];        // h2 over row range (mirror)
        ss[tid]       = g_s[0][gm + tid];
        ss[64 + tid]  = g_s[1][gn + tid];
        ss[128 + tid] = g_s[0][gn + tid];
        ss[192 + tid] = g_s[1][gm + tid];
    }

    #pragma unroll 1
    for (int bi = 0; bi < 4; bi++) {
        int b = bg * 4 + bi;
        __syncthreads();                         // prev iter's tile reads done (and hh/ss ready)
        // ---- stage tiles for this batch ----
        const __nv_bfloat16* gHi = g_Ah + (size_t)b * C * KP;
        const __nv_bfloat16* gLo = g_Al + (size_t)b * C * KP;
        {
            const __nv_bfloat16* sa_h = gHi + (size_t)ti * 64 * KP;
            const __nv_bfloat16* sa_l = gLo + (size_t)ti * 64 * KP;
            const __nv_bfloat16* sb_h = gHi + (size_t)tj * 64 * KP;
            const __nv_bfloat16* sb_l = gLo + (size_t)tj * 64 * KP;
            #pragma unroll 2
            for (int idx = tid; idx < 64 * 26; idx += 256) {
                int row = idx / 26, q = idx - row * 26;
                int so = row * KP + q * 8, dof = row * LDK + q * 8;
                *(uint4*)&Ahi[dof] = *(const uint4*)&sa_h[so];
                *(uint4*)&Ali[dof] = *(const uint4*)&sa_l[so];
                if (!diag) {
                    *(uint4*)&Bhj[dof] = *(const uint4*)&sb_h[so];
                    *(uint4*)&Blj[dof] = *(const uint4*)&sb_l[so];
                }
            }
        }
        __syncthreads();

        const __nv_bfloat16* Ph = diag ? Ahi : Bhj;
        const __nv_bfloat16* Pl = diag ? Ali : Blj;

        // 2 output tiles x 3 independent product chains
        wmma::fragment<wmma::accumulator, 16, 16, 16, float> a0hh, a0hl, a0lh, a1hh, a1hl, a1lh;
        wmma::fill_fragment(a0hh, 0.f); wmma::fill_fragment(a0hl, 0.f); wmma::fill_fragment(a0lh, 0.f);
        wmma::fill_fragment(a1hh, 0.f); wmma::fill_fragment(a1hl, 0.f); wmma::fill_fragment(a1lh, 0.f);

        #pragma unroll
        for (int kc = 0; kc < 13; kc++) {
            int ko = kc * 16;
            wmma::fragment<wmma::matrix_a, 16, 16, 16, __nv_bfloat16, wmma::row_major> ah, al;
            wmma::fragment<wmma::matrix_b, 16, 16, 16, __nv_bfloat16, wmma::col_major> bh0, bh1, bl0, bl1;
            wmma::load_matrix_sync(ah,  &Ahi[(wr * 16) * LDK + ko], LDK);
            wmma::load_matrix_sync(al,  &Ali[(wr * 16) * LDK + ko], LDK);
            wmma::load_matrix_sync(bh0, &Ph[(wc * 32) * LDK + ko], LDK);
            wmma::load_matrix_sync(bh1, &Ph[(wc * 32 + 16) * LDK + ko], LDK);
            wmma::load_matrix_sync(bl0, &Pl[(wc * 32) * LDK + ko], LDK);
            wmma::load_matrix_sync(bl1, &Pl[(wc * 32 + 16) * LDK + ko], LDK);
            wmma::mma_sync(a0hh, ah, bh0, a0hh);     // all 6 independent
            wmma::mma_sync(a1hh, ah, bh1, a1hh);
            wmma::mma_sync(a0hl, ah, bl0, a0hl);
            wmma::mma_sync(a1hl, ah, bl1, a1hl);
            wmma::mma_sync(a0lh, al, bh0, a0lh);
            wmma::mma_sync(a1lh, al, bh1, a1lh);
        }
        #pragma unroll
        for (int e = 0; e < a0hh.num_elements; e++) {
            a0hh.x[e] += a0hl.x[e] + a0lh.x[e];
            a1hh.x[e] += a1hl.x[e] + a1lh.x[e];
        }

        float* st = stage + bi * STAGE_F;
        wmma::store_matrix_sync(&st[(wr * 16) * LDS2 + wc * 32],      a0hh, LDS2, wmma::mem_row_major);
        wmma::store_matrix_sync(&st[(wr * 16) * LDS2 + wc * 32 + 16], a1hh, LDS2, wmma::mem_row_major);
    }
    __syncthreads();

    // ---- scatter: one red.v4 per (pair, orientation) covering 4 batches ----
    float* Ybase = g_Yt + bg * 4;
    #pragma unroll 4
    for (int e = tid; e < 4096; e += 256) {
        int r = e >> 6, c = e & 63;
        int off = r * LDS2 + c;
        float v0 = stage[0 * STAGE_F + off];
        float v1 = stage[1 * STAGE_F + off];
        float v2 = stage[2 * STAGE_F + off];
        float v3 = stage[3 * STAGE_F + off];
        int   d1 = (hh[r] + hh[64 + c]) & (D - 1);
        float w1 = ss[r] * ss[64 + c];
        float* p1 = Ybase + (size_t)d1 * B;
        asm volatile("red.global.add.v4.f32 [%0], {%1, %2, %3, %4};"
                     :: "l"(p1), "f"(v0 * w1), "f"(v1 * w1), "f"(v2 * w1), "f"(v3 * w1)
                     : "memory");
        if (!diag) {
            int   d2 = (hh[128 + c] + hh[192 + r]) & (D - 1);
            float w2 = ss[128 + c] * ss[192 + r];
            float* p2 = Ybase + (size_t)d2 * B;
            asm volatile("red.global.add.v4.f32 [%0], {%1, %2, %3, %4};"
                         :: "l"(p2), "f"(v0 * w2), "f"(v1 * w2), "f"(v2 * w2), "f"(v3 * w2)
                         : "memory");
        }
    }
}

// ---------------- 3a. signed sqrt + transpose + per-batch sumsq (coalesced) ----------------
__global__ void sqrt_transpose_kernel() {        // 256 blocks x 256 thr, 32d x 32b tiles
    __shared__ float tile[32][36];
    __shared__ float snorm[B];
    int t  = threadIdx.x;
    int d0 = blockIdx.x * 32;
    if (t < B) snorm[t] = 0.f;
    __syncthreads();

    float4 v = ((const float4*)(g_Yt + (size_t)d0 * B))[t];  // coalesced: 1024 floats
    int dl = t >> 3;             // d within tile
    int b0 = (t & 7) * 4;        // first of 4 consecutive b
    float vv[4] = {v.x, v.y, v.z, v.w};
    float sq = 0.f;
    #pragma unroll
    for (int k = 0; k < 4; k++) {
        float y  = vv[k];
        float sg = (y > 0.f) ? 1.f : ((y < 0.f) ? -1.f : 0.f);
        float s  = sg * sqrtf(fabsf(y) + 1e-8f);
        tile[b0 + k][dl] = s;
        atomicAdd(&snorm[b0 + k], s * s);
        (void)sq;
    }
    __syncthreads();
    if (t < B) atomicAdd(&g_norm[t], snorm[t]);
    // transposed write: thread t -> (b = t>>3, 4 d's at q*4)
    int b = t >> 3, q = t & 7;
    float4 w = *(float4*)&tile[b][q * 4];
    ((float4*)(g_Ys + (size_t)b * D + d0))[q] = w;
}

// ---------------- 3b. L2 normalize (coalesced) ----------------
__global__ void normalize_kernel(float* __restrict__ out) {  // 256 blocks x 256 thr
    int b  = blockIdx.x >> 3;
    int d0 = (blockIdx.x & 7) * 1024;
    int t  = threadIdx.x;
    float inv = 1.f / fmaxf(sqrtf(g_norm[b]), 1e-12f);
    float4 v = ((const float4*)(g_Ys + (size_t)b * D + d0))[t];
    v.x *= inv; v.y *= inv; v.z *= inv; v.w *= inv;
    ((float4*)(out + (size_t)b * D + d0))[t] = v;
}

// ---------------- launcher ----------------
extern "C" void kernel_launch(void* const* d_in, const int* in_sizes, int n_in,
                              void* d_out, int out_size) {
    const float* x  = nullptr;
    const float* S1 = nullptr;
    const float* S2 = nullptr;
    for (int i = 0; i < n_in; i++) {
        if (in_sizes[i] == B * C * HW) { x = (const float*)d_in[i]; }
        else if (!S1)                  { S1 = (const float*)d_in[i]; }
        else                           { S2 = (const float*)d_in[i]; }
    }
    float* out = (float*)d_out;

    static int smem_set = 0;
    if (!smem_set) {
        cudaFuncSetAttribute(gram_scatter, cudaFuncAttributeMaxDynamicSharedMemorySize, SMEM_DYN);
        smem_set = 1;
    }

    setup_kernel         <<<1024 + 2048 + 256, 256>>>(x, S1, S2);   // idx 0
    dummy_kernel         <<<1, 32>>>();                              // idx 1
    dummy_kernel         <<<1, 32>>>();                              // idx 2
    gram_scatter         <<<dim3(36, 8), 256, SMEM_DYN>>>();         // idx 3 <- ncu sample
    sqrt_transpose_kernel<<<256, 256>>>();
    normalize_kernel     <<<256, 256>>>(out);
}

// round 16
// speedup vs baseline: 1.6261x; 1.3885x over previous
#include <cuda_runtime.h>
#include <cuda_fp16.h>
#include <mma.h>
#include <math.h>

using namespace nvcuda;

// Problem constants
#define B   32
#define C   512
#define HW  196          // 14*14
#define D   8192
#define KP  208          // HW padded to 13*16
#define BC  (B * C)      // 16384
#define LDS2 68          // stage row stride (floats)
#define STAGE_F (64 * LDS2)              // floats per batch stage
// K-halved tiles: half0 = 112 cols (7 chunks), half1 = 96 cols (6 chunks)
#define LDKH 120         // half-tile smem row stride (elems), %8==0
#define TILE_H (64 * LDKH)               // elems per half tile (7680)
#define SMEM_DYN (2*TILE_H*2 + 4*STAGE_F*4)   // 30720 + 69632 = 100352

// ---------------- device scratch (no allocations allowed) ----------------
__device__ int   g_h[2][C];
__device__ float g_s[2][C];
__device__ __align__(32) __half g_Xh[(size_t)BC * KP];   // fp16 copy of x (K-padded)
__device__ float g_Yt[(size_t)D * B];           // [d][b]  (b innermost)
__device__ float g_Ys[(size_t)B * D];           // signed-sqrt values, [b][d]
__device__ float g_norm[B];                      // per-batch sum of squares

// ---------------- 0. dummy: positions gram_scatter at global launch index 3 ----------------
__global__ void dummy_kernel() {}

// ---------------- 1. fused: fp16-pack x, extract (h,s), zero Yt/norm ----------------
__global__ void setup_kernel(const float* __restrict__ x,
                             const float* __restrict__ S1,
                             const float* __restrict__ S2) {
    int bx = blockIdx.x;
    int t  = threadIdx.x;
    if (bx < 1024) {
        // ---- prep: 16 x-rows per block, convert to fp16 ----
        int base = bx * 16;
        for (int e = t; e < 16 * KP; e += 256) {
            int r = e / KP, k = e - r * KP;
            int bc = base + r;
            float v = (k < HW) ? x[(size_t)bc * HW + k] : 0.f;
            g_Xh[(size_t)bc * KP + k] = __float2half(v);
        }
        return;
    }
    if (bx < 1024 + 2048) {
        // ---- extract: 2 blocks per sketch row; 4 independent loads (MLP=4) ----
        int q    = bx - 1024;
        int row  = q >> 1;
        int half = q & 1;
        int mat = row >> 9;
        int r   = row & (C - 1);
        const float4* p = (const float4*)((mat ? S2 : S1) + (size_t)r * D) + half * 1024;
        float4 v[4];
        #pragma unroll
        for (int u = 0; u < 4; u++) v[u] = p[t + u * 256];
        int   idx = -1;
        float sg  = 0.f;
        #pragma unroll
        for (int u = 0; u < 4; u++) {
            int c = half * 4096 + 4 * (t + u * 256);
            if (fabsf(v[u].x) > 0.5f) { idx = c + 0; sg = v[u].x; }
            if (fabsf(v[u].y) > 0.5f) { idx = c + 1; sg = v[u].y; }
            if (fabsf(v[u].z) > 0.5f) { idx = c + 2; sg = v[u].z; }
            if (fabsf(v[u].w) > 0.5f) { idx = c + 3; sg = v[u].w; }
        }
        if (idx >= 0) {                          // exactly one thread (whole grid) hits per row
            g_h[mat][r] = idx;
            g_s[mat][r] = sg;
        }
        return;
    }
    // ---- zero Yt (+ norm): 256 blocks x 256 thr x float4 ----
    int zb = bx - 1024 - 2048;
    float4* y4 = (float4*)g_Yt;
    y4[zb * 256 + t] = make_float4(0.f, 0.f, 0.f, 0.f);
    if (zb == 0 && t < B) g_norm[t] = 0.f;
}

// ---------------- 2. Gram (fp16 wmma), K-halved tiles, 4-batch groups, v4 red scatter ----
__global__ __launch_bounds__(256, 2) void gram_scatter() {
    int bg = blockIdx.y;                         // batch group: b = bg*4 + bi
    int ti = 0, rem = blockIdx.x;                // upper-triangular tile pair, ti <= tj
    while (rem >= 8 - ti) { rem -= 8 - ti; ti++; }
    int tj = ti + rem;
    bool diag = (ti == tj);

    extern __shared__ __align__(16) __half sm[];
    __half* Ah = sm;                             // 64 x LDKH
    __half* Bh = sm + TILE_H;                    // 64 x LDKH
    float* stage = (float*)(sm + 2 * TILE_H);    // 4 x (64 x LDS2) floats
    __shared__ int   hh[256];
    __shared__ float ss[256];

    int tid  = threadIdx.x;
    int warp = tid >> 5;
    int wr   = warp >> 1;        // 0..3 (m, 16 rows)
    int wc   = warp & 1;         // 0..1 (n, 32 cols)

    int gm = ti * 64, gn = tj * 64;
    if (tid < 64) {
        hh[tid]       = g_h[0][gm + tid];        // h1 over row range
        hh[64 + tid]  = g_h[1][gn + tid];        // h2 over col range
        hh[128 + tid] = g_h[0][gn + tid];        // h1 over col range (mirror)
        hh[192 + tid] = g_h[1][gm + tid];        // h2 over row range (mirror)
        ss[tid]       = g_s[0][gm + tid];
        ss[64 + tid]  = g_s[1][gn + tid];
        ss[128 + tid] = g_s[0][gn + tid];
        ss[192 + tid] = g_s[1][gm + tid];
    }

    const __half* Ph = diag ? Ah : Bh;

    #pragma unroll 1
    for (int bi = 0; bi < 4; bi++) {
        int b = bg * 4 + bi;

        wmma::fragment<wmma::accumulator, 16, 16, 16, float> acc0, acc1;
        wmma::fill_fragment(acc0, 0.f);
        wmma::fill_fragment(acc1, 0.f);

        #pragma unroll 1
        for (int h = 0; h < 2; h++) {
            int kbase = h * 112;                 // global k offset of this half
            int nvec  = h ? 12 : 14;             // uint4 (8 halfs) per row
            int nch   = h ? 6 : 7;               // 16-wide MMA chunks in this half
            __syncthreads();                     // prev MMA reads done (and hh/ss ready)
            // ---- stage half-tiles ----
            {
                const __half* srcA = g_Xh + ((size_t)b * C + gm) * KP + kbase;
                const __half* srcB = g_Xh + ((size_t)b * C + gn) * KP + kbase;
                int tot = 64 * nvec;
                #pragma unroll 2
                for (int e = tid; e < tot; e += 256) {
                    int row = e / nvec, q = e - row * nvec;
                    *(uint4*)&Ah[row * LDKH + q * 8] = *(const uint4*)&srcA[(size_t)row * KP + q * 8];
                    if (!diag)
                        *(uint4*)&Bh[row * LDKH + q * 8] = *(const uint4*)&srcB[(size_t)row * KP + q * 8];
                }
            }
            __syncthreads();

            #pragma unroll
            for (int c = 0; c < 7; c++) {
                if (c >= nch) break;
                int ko = c * 16;
                wmma::fragment<wmma::matrix_a, 16, 16, 16, __half, wmma::row_major> af;
                wmma::fragment<wmma::matrix_b, 16, 16, 16, __half, wmma::col_major> bf0, bf1;
                wmma::load_matrix_sync(af,  &Ah[(wr * 16) * LDKH + ko], LDKH);
                wmma::load_matrix_sync(bf0, &Ph[(wc * 32) * LDKH + ko], LDKH);
                wmma::load_matrix_sync(bf1, &Ph[(wc * 32 + 16) * LDKH + ko], LDKH);
                wmma::mma_sync(acc0, af, bf0, acc0);
                wmma::mma_sync(acc1, af, bf1, acc1);
            }
        }

        float* st = stage + bi * STAGE_F;
        wmma::store_matrix_sync(&st[(wr * 16) * LDS2 + wc * 32],      acc0, LDS2, wmma::mem_row_major);
        wmma::store_matrix_sync(&st[(wr * 16) * LDS2 + wc * 32 + 16], acc1, LDS2, wmma::mem_row_major);
    }
    __syncthreads();

    // ---- scatter: one red.v4 per (pair, orientation) covering 4 batches ----
    float* Ybase = g_Yt + bg * 4;
    #pragma unroll 4
    for (int e = tid; e < 4096; e += 256) {
        int r = e >> 6, c = e & 63;
        int off = r * LDS2 + c;
        float v0 = stage[0 * STAGE_F + off];
        float v1 = stage[1 * STAGE_F + off];
        float v2 = stage[2 * STAGE_F + off];
        float v3 = stage[3 * STAGE_F + off];
        int   d1 = (hh[r] + hh[64 + c]) & (D - 1);
        float w1 = ss[r] * ss[64 + c];
        float* p1 = Ybase + (size_t)d1 * B;
        asm volatile("red.global.add.v4.f32 [%0], {%1, %2, %3, %4};"
                     :: "l"(p1), "f"(v0 * w1), "f"(v1 * w1), "f"(v2 * w1), "f"(v3 * w1)
                     : "memory");
        if (!diag) {
            int   d2 = (hh[128 + c] + hh[192 + r]) & (D - 1);
            float w2 = ss[128 + c] * ss[192 + r];
            float* p2 = Ybase + (size_t)d2 * B;
            asm volatile("red.global.add.v4.f32 [%0], {%1, %2, %3, %4};"
                         :: "l"(p2), "f"(v0 * w2), "f"(v1 * w2), "f"(v2 * w2), "f"(v3 * w2)
                         : "memory");
        }
    }
}

// ---------------- 3a. signed sqrt + transpose + per-batch sumsq (coalesced) ----------------
__global__ void sqrt_transpose_kernel() {        // 256 blocks x 256 thr, 32d x 32b tiles
    __shared__ float tile[32][36];
    __shared__ float snorm[B];
    int t  = threadIdx.x;
    int d0 = blockIdx.x * 32;
    if (t < B) snorm[t] = 0.f;
    __syncthreads();

    float4 v = ((const float4*)(g_Yt + (size_t)d0 * B))[t];  // coalesced: 1024 floats
    int dl = t >> 3;             // d within tile
    int b0 = (t & 7) * 4;        // first of 4 consecutive b
    float vv[4] = {v.x, v.y, v.z, v.w};
    #pragma unroll
    for (int k = 0; k < 4; k++) {
        float y  = vv[k];
        float sg = (y > 0.f) ? 1.f : ((y < 0.f) ? -1.f : 0.f);
        float s  = sg * sqrtf(fabsf(y) + 1e-8f);
        tile[b0 + k][dl] = s;
        atomicAdd(&snorm[b0 + k], s * s);
    }
    __syncthreads();
    if (t < B) atomicAdd(&g_norm[t], snorm[t]);
    int b = t >> 3, q = t & 7;
    float4 w = *(float4*)&tile[b][q * 4];
    ((float4*)(g_Ys + (size_t)b * D + d0))[q] = w;
}

// ---------------- 3b. L2 normalize (coalesced) ----------------
__global__ void normalize_kernel(float* __restrict__ out) {  // 256 blocks x 256 thr
    int b  = blockIdx.x >> 3;
    int d0 = (blockIdx.x & 7) * 1024;
    int t  = threadIdx.x;
    float inv = 1.f / fmaxf(sqrtf(g_norm[b]), 1e-12f);
    float4 v = ((const float4*)(g_Ys + (size_t)b * D + d0))[t];
    v.x *= inv; v.y *= inv; v.z *= inv; v.w *= inv;
    ((float4*)(out + (size_t)b * D + d0))[t] = v;
}

// ---------------- launcher ----------------
extern "C" void kernel_launch(void* const* d_in, const int* in_sizes, int n_in,
                              void* d_out, int out_size) {
    const float* x  = nullptr;
    const float* S1 = nullptr;
    const float* S2 = nullptr;
    for (int i = 0; i < n_in; i++) {
        if (in_sizes[i] == B * C * HW) { x = (const float*)d_in[i]; }
        else if (!S1)                  { S1 = (const float*)d_in[i]; }
        else                           { S2 = (const float*)d_in[i]; }
    }
    float* out = (float*)d_out;

    static int smem_set = 0;
    if (!smem_set) {
        cudaFuncSetAttribute(gram_scatter, cudaFuncAttributeMaxDynamicSharedMemorySize, SMEM_DYN);
        smem_set = 1;
    }

    setup_kernel         <<<1024 + 2048 + 256, 256>>>(x, S1, S2);   // idx 0
    dummy_kernel         <<<1, 32>>>();                              // idx 1
    dummy_kernel         <<<1, 32>>>();                              // idx 2
    gram_scatter         <<<dim3(36, 8), 256, SMEM_DYN>>>();         // idx 3 <- ncu sample
    sqrt_transpose_kernel<<<256, 256>>>();
    normalize_kernel     <<<256, 256>>>(out);
}